// round 12
// baseline (speedup 1.0000x reference)
#include <cuda_runtime.h>
#include <cuda_bf16.h>
#include <cstdint>

// Problem constants
#define NN   32
#define CC   512
#define TT   1024
#define NTOK 32768            // NN*TT
#define NB   2048
#define MU   0.99f
#define OMU  0.01f
#define MARGIN 12.0f
#define LCAP 3072

// Output layout (concatenated, all f32)
#define OFF_XD    ((size_t)0)
#define OFF_LOSS  ((size_t)16777216)
#define OFF_PERP  ((size_t)16777217)
#define OFF_CB    ((size_t)16777218)
#define OFF_SEMA  ((size_t)17825794)
#define OFF_CEMA  ((size_t)18874370)

// ---------------- device scratch (no allocs allowed) ----------------
__device__ float g_cbnorm[NB];
__device__ float g_sum[(size_t)NB * CC];
__device__ float g_cnt[NB];
__device__ float g_loss;
__device__ __align__(16) __nv_bfloat16 g_xhi[(size_t)NTOK * CC];
__device__ __align__(16) float         g_xT [(size_t)NTOK * CC];   // fp32 transposed x
__device__ __align__(16) __nv_bfloat16 g_bhi[(size_t)NB * CC];

// ---------------- PTX helpers ----------------
__device__ __forceinline__ uint32_t smem_u32(const void* p) {
    uint32_t a;
    asm("{ .reg .u64 t; cvta.to.shared.u64 t, %1; cvt.u32.u64 %0, t; }" : "=r"(a) : "l"(p));
    return a;
}
__device__ __forceinline__ void cp16(uint32_t dst, const void* src) {
    asm volatile("cp.async.cg.shared.global [%0], [%1], 16;" :: "r"(dst), "l"(src));
}
__device__ __forceinline__ void ldmx4(uint32_t* r, uint32_t addr) {
    asm volatile("ldmatrix.sync.aligned.m8n8.x4.shared.b16 {%0,%1,%2,%3}, [%4];"
                 : "=r"(r[0]), "=r"(r[1]), "=r"(r[2]), "=r"(r[3]) : "r"(addr));
}
__device__ __forceinline__ void mma16816(float* d, const uint32_t* a, const uint32_t* b) {
    asm volatile(
        "mma.sync.aligned.m16n8k16.row.col.f32.bf16.bf16.f32 "
        "{%0,%1,%2,%3}, {%4,%5,%6,%7}, {%8,%9}, {%0,%1,%2,%3};"
        : "+f"(d[0]), "+f"(d[1]), "+f"(d[2]), "+f"(d[3])
        : "r"(a[0]), "r"(a[1]), "r"(a[2]), "r"(a[3]), "r"(b[0]), "r"(b[1]));
}
// order-preserving float<->uint
__device__ __forceinline__ unsigned f2u(float f) {
    unsigned u = __float_as_uint(f);
    return (u & 0x80000000u) ? ~u : (u | 0x80000000u);
}
__device__ __forceinline__ float u2f(unsigned u) {
    return (u & 0x80000000u) ? __uint_as_float(u & 0x7FFFFFFFu)
                             : __uint_as_float(~u);
}

// ---------------- zero scratch ----------------
__global__ void k_zero() {
    int i = blockIdx.x * blockDim.x + threadIdx.x;
    const int total = NB * CC + NB + 1;
    for (; i < total; i += gridDim.x * blockDim.x) {
        if (i < NB * CC)           g_sum[i] = 0.0f;
        else if (i < NB * CC + NB) g_cnt[i - NB * CC] = 0.0f;
        else                       g_loss = 0.0f;
    }
}

// ---------------- codebook: bf16 hi + exact fp32 norms ----------
__global__ __launch_bounds__(256) void k_convert_cb(const float* __restrict__ cb) {
    int wid  = (blockIdx.x * blockDim.x + threadIdx.x) >> 5;
    int lane = threadIdx.x & 31;
    if (wid >= NB) return;
    const float* row = cb + (size_t)wid * CC;
    float s = 0.0f;
    #pragma unroll
    for (int i = 0; i < CC / 32; i++) {
        float v = row[lane + 32 * i];
        s += v * v;
        g_bhi[(size_t)wid * CC + lane + 32 * i] = __float2bfloat16(v);
    }
    #pragma unroll
    for (int o = 16; o > 0; o >>= 1) s += __shfl_down_sync(0xFFFFFFFFu, s, o);
    if (lane == 0) g_cbnorm[wid] = s;
}

// ---------------- transpose x: bf16 hi + fp32 copy ----------------
__global__ __launch_bounds__(256) void k_convert_x(const float* __restrict__ x) {
    __shared__ float s[64][65];
    const int b = blockIdx.x;
    const int ttile = b & 15, ctile = (b >> 4) & 7, n = b >> 7;
    const int c0 = ctile * 64, t0 = ttile * 64;
    const int tid = threadIdx.x;
    const float* xb = x + (size_t)n * CC * TT;
    #pragma unroll
    for (int q = 0; q < 16; q++) {
        int idx = tid + 256 * q;
        int r = idx >> 6, col = idx & 63;
        s[r][col] = xb[(size_t)(c0 + r) * TT + t0 + col];
    }
    __syncthreads();
    #pragma unroll
    for (int q = 0; q < 16; q++) {
        int idx = tid + 256 * q;
        int tr = idx >> 6, cc = idx & 63;
        float v = s[cc][tr];
        size_t token = (size_t)(n * 1024 + t0 + tr);
        g_xhi[token * 512 + c0 + cc] = __float2bfloat16(v);
        g_xT [token * 512 + c0 + cc] = v;
    }
}

// ---------------- approx GEMM + candidate collect + exact rescore + scatter
// Block: 128 tokens x 128-code tile, 16 code tiles, K = 512 (hi only).
// 4 warps (2x2), warp tile 64x64. 3-stage cp.async ring, BK = 64.
#define STAGE 32768
#define HMMA_SMEM (3 * STAGE)
#define NSTEPS 128              // 16 nj * 8 k-steps

__device__ __forceinline__ void load_tile(int tid, uint32_t dyn, int it, int m0) {
    const int nj = it >> 3;
    const int kt = it & 7;
    const __nv_bfloat16* Asrc = g_xhi + (size_t)m0 * 512 + kt * 64;
    const __nv_bfloat16* Bsrc = g_bhi + (size_t)nj * 128 * 512 + kt * 64;
    const uint32_t abase = dyn + (uint32_t)(it % 3) * STAGE;
    const uint32_t bbase = abase + 16384u;
    #pragma unroll
    for (int q = 0; q < 8; q++) {
        int op = tid + 128 * q;
        int row = op >> 3, c = op & 7;
        cp16(abase + row * 128 + (((c ^ row) & 7) << 4), Asrc + (size_t)row * 512 + c * 8);
    }
    #pragma unroll
    for (int q = 0; q < 8; q++) {
        int op = tid + 128 * q;
        int row = op >> 3, c = op & 7;
        cp16(bbase + row * 128 + (((c ^ row) & 7) << 4), Bsrc + (size_t)row * 512 + c * 8);
    }
    asm volatile("cp.async.commit_group;" ::: "memory");
}

__global__ __launch_bounds__(128, 2) void k_hmma(const float* __restrict__ x,
                                                 const float* __restrict__ cb,
                                                 float* __restrict__ out) {
    extern __shared__ char dsm[];
    __shared__ unsigned sMinU[128];            // running approx min (ordered uint)
    __shared__ float    sNorm[128];            // this nj-tile's codebook norms
    __shared__ unsigned long long sKeyE[128];  // exact (d,j) keys
    __shared__ unsigned sList[LCAP];           // candidates: row<<16 | j
    __shared__ int  sCnt;
    __shared__ int  sIdx[128];
    __shared__ float sRed[128];

    const uint32_t dyn = smem_u32(dsm);
    const int tid  = threadIdx.x;
    const int lane = tid & 31;
    const int warp = tid >> 5;
    const int wm   = warp >> 1;      // 0..1
    const int wn   = warp & 1;       // 0..1
    const int m0   = blockIdx.x * 128;

    // init shared state
    sMinU[tid] = 0xFFFFFFFFu;
    sKeyE[tid] = 0xFFFFFFFFFFFFFFFFULL;
    if (tid == 0) sCnt = 0;

    // ldmatrix per-thread addressing
    const int sub = lane >> 3, l7 = lane & 7;
    const int a_rowadd = ((sub & 1) << 3) + l7;
    const int a_cadd   = sub >> 1;
    const int b_rowadd = ((sub >> 1) << 3) + l7;
    const int b_cadd   = sub & 1;
    uint32_t aRowB[4], bRowB[4];
    #pragma unroll
    for (int mt = 0; mt < 4; mt++) aRowB[mt] = (uint32_t)(wm * 64 + mt * 16 + a_rowadd) * 128u;
    #pragma unroll
    for (int p = 0; p < 4; p++)    bRowB[p] = (uint32_t)(wn * 64 + p * 16 + b_rowadd) * 128u;

    float acc[4][8][4];
    #pragma unroll
    for (int mt = 0; mt < 4; mt++)
        #pragma unroll
        for (int nt = 0; nt < 8; nt++)
            #pragma unroll
            for (int r = 0; r < 4; r++) acc[mt][nt][r] = 0.0f;

    load_tile(tid, dyn, 0, m0);
    load_tile(tid, dyn, 1, m0);

    for (int it = 0; it < NSTEPS; it++) {
        if (it + 1 < NSTEPS) asm volatile("cp.async.wait_group 1;" ::: "memory");
        else                 asm volatile("cp.async.wait_group 0;" ::: "memory");
        __syncthreads();
        if (it + 2 < NSTEPS) load_tile(tid, dyn, it + 2, m0);

        // first k-step of a code tile: stage its norms into SMEM
        // (prev tile's readers finished before this iteration's barrier)
        if ((it & 7) == 0) sNorm[tid] = g_cbnorm[(it >> 3) * 128 + tid];

        const uint32_t abase = dyn + (uint32_t)(it % 3) * STAGE;
        const uint32_t bbase = abase + 16384u;

        #pragma unroll
        for (int kk = 0; kk < 4; kk++) {
            uint32_t afr[4][4], bfr[4][4];
            #pragma unroll
            for (int mt = 0; mt < 4; mt++)
                ldmx4(afr[mt], abase + aRowB[mt] + ((((kk * 2 + a_cadd) ^ l7) & 7) << 4));
            #pragma unroll
            for (int p = 0; p < 4; p++)
                ldmx4(bfr[p], bbase + bRowB[p] + ((((kk * 2 + b_cadd) ^ l7) & 7) << 4));
            #pragma unroll
            for (int mt = 0; mt < 4; mt++)
                #pragma unroll
                for (int nt = 0; nt < 8; nt++)
                    mma16816(acc[mt][nt], afr[mt], &bfr[nt >> 1][(nt & 1) * 2]);
        }

        // end of one nj code-tile: single-pass fold + candidate collect
        if ((it & 7) == 7) {
            const int njbase = (it >> 3) * 128;

            if (it == 7) {
                // nj==0 only: pre-fold so thresholds are finite
                #pragma unroll
                for (int mt = 0; mt < 4; mt++) {
                    #pragma unroll
                    for (int rh = 0; rh < 2; rh++) {
                        unsigned bu = 0xFFFFFFFFu;
                        #pragma unroll
                        for (int nt = 0; nt < 8; nt++) {
                            #pragma unroll
                            for (int c = 0; c < 2; c++) {
                                int jl = wn * 64 + nt * 8 + ((lane & 3) << 1) + c;
                                float d = fmaf(-2.0f, acc[mt][nt][rh * 2 + c], sNorm[jl]);
                                bu = min(bu, f2u(d));
                            }
                        }
                        bu = min(bu, __shfl_xor_sync(0xFFFFFFFFu, bu, 1));
                        bu = min(bu, __shfl_xor_sync(0xFFFFFFFFu, bu, 2));
                        if ((lane & 3) == 0)
                            atomicMin(&sMinU[wm * 64 + mt * 16 + rh * 8 + (lane >> 2)], bu);
                    }
                }
                __syncthreads();
            }

            // combined pass: stale-min threshold is provably safe
            #pragma unroll
            for (int mt = 0; mt < 4; mt++) {
                #pragma unroll
                for (int rh = 0; rh < 2; rh++) {
                    const int row = wm * 64 + mt * 16 + rh * 8 + (lane >> 2);
                    const float thr = u2f(sMinU[row]) + MARGIN;
                    unsigned bu = 0xFFFFFFFFu;
                    #pragma unroll
                    for (int nt = 0; nt < 8; nt++) {
                        #pragma unroll
                        for (int c = 0; c < 2; c++) {
                            int jl = wn * 64 + nt * 8 + ((lane & 3) << 1) + c;
                            float d = fmaf(-2.0f, acc[mt][nt][rh * 2 + c], sNorm[jl]);
                            bu = min(bu, f2u(d));
                            // warp-aggregated push
                            unsigned mk = __ballot_sync(0xFFFFFFFFu, d <= thr);
                            if (mk) {
                                int base;
                                if (lane == 0) base = atomicAdd(&sCnt, __popc(mk));
                                base = __shfl_sync(0xFFFFFFFFu, base, 0);
                                if (d <= thr) {
                                    int pos = base + __popc(mk & ((1u << lane) - 1u));
                                    if (pos < LCAP)
                                        sList[pos] = ((unsigned)row << 16)
                                                   | (unsigned)(njbase + jl);
                                }
                            }
                        }
                    }
                    bu = min(bu, __shfl_xor_sync(0xFFFFFFFFu, bu, 1));
                    bu = min(bu, __shfl_xor_sync(0xFFFFFFFFu, bu, 2));
                    if ((lane & 3) == 0) atomicMin(&sMinU[row], bu);
                }
            }

            #pragma unroll
            for (int mt = 0; mt < 4; mt++)
                #pragma unroll
                for (int nt = 0; nt < 8; nt++)
                    #pragma unroll
                    for (int r = 0; r < 4; r++) acc[mt][nt][r] = 0.0f;
        }
    }

    __syncthreads();
    // -------- pass 2: exact fp32 rescore of candidates ------------------
    {
        const int cnt = min(sCnt, LCAP);
        for (int i = warp; i < cnt; i += 4) {
            unsigned e = sList[i];
            int row = e >> 16;
            int j   = e & 0xFFFF;
            const float4* xr = (const float4*)(g_xT + (size_t)(m0 + row) * 512);
            const float4* cr = (const float4*)(cb  + (size_t)j * 512);
            float s = 0.0f;
            #pragma unroll
            for (int q = 0; q < 4; q++) {
                float4 a = xr[lane + 32 * q];
                float4 b = cr[lane + 32 * q];
                s += a.x * b.x + a.y * b.y + a.z * b.z + a.w * b.w;
            }
            #pragma unroll
            for (int o = 16; o > 0; o >>= 1) s += __shfl_xor_sync(0xFFFFFFFFu, s, o);
            if (lane == 0) {
                float d = fmaf(-2.0f, s, g_cbnorm[j]);
                unsigned long long key = ((unsigned long long)f2u(d) << 32) | (unsigned)j;
                atomicMin(&sKeyE[row], key);
            }
        }
    }
    __syncthreads();
    {
        int id = (int)(sKeyE[tid] & 0xFFFFFFFFu);
        sIdx[tid] = id;
        atomicAdd(&g_cnt[id], 1.0f);
    }
    __syncthreads();

    // -------- fused scatter: this CTA's 128 tokens, all 512 channels -----
    {
        const int n  = m0 >> 10;
        const int t0 = m0 & 1023;
        const int idx  = sIdx[tid];
        const float* xb = x + (size_t)n * CC * TT + t0 + tid;
        float* ob = out + OFF_XD + (size_t)n * CC * TT + t0 + tid;
        const float* cbrow = cb + (size_t)idx * CC;
        float* srow = g_sum + (size_t)idx * CC;

        float loss = 0.0f;
        #pragma unroll 8
        for (int k = 0; k < 128; k++) {
            int c = k * 4;
            float4 cv = *(const float4*)(cbrow + c);
            float x0 = __ldcs(xb + (size_t)(c + 0) * TT);
            float x1 = __ldcs(xb + (size_t)(c + 1) * TT);
            float x2 = __ldcs(xb + (size_t)(c + 2) * TT);
            float x3 = __ldcs(xb + (size_t)(c + 3) * TT);
            float d0 = x0 - cv.x, d1 = x1 - cv.y, d2 = x2 - cv.z, d3 = x3 - cv.w;
            loss = fmaf(d0, d0, loss); loss = fmaf(d1, d1, loss);
            loss = fmaf(d2, d2, loss); loss = fmaf(d3, d3, loss);
            __stcs(ob + (size_t)(c + 0) * TT, x0 + (cv.x - x0));
            __stcs(ob + (size_t)(c + 1) * TT, x1 + (cv.y - x1));
            __stcs(ob + (size_t)(c + 2) * TT, x2 + (cv.z - x2));
            __stcs(ob + (size_t)(c + 3) * TT, x3 + (cv.w - x3));
            asm volatile("red.global.add.v4.f32 [%0], {%1, %2, %3, %4};"
                         :: "l"(srow + c), "f"(x0), "f"(x1), "f"(x2), "f"(x3) : "memory");
        }

        sRed[tid] = loss;
        __syncthreads();
        for (int o = 64; o > 0; o >>= 1) {
            if (tid < o) sRed[tid] += sRed[tid + o];
            __syncthreads();
        }
        if (tid == 0) atomicAdd(&g_loss, sRed[0]);
    }
}

// ---------------- EMA + codebook (+ scalars in block 0) ----------------
__global__ __launch_bounds__(256) void k_ema(const float* __restrict__ x,
                                             const float* __restrict__ code_sum_in,
                                             const float* __restrict__ code_count_in,
                                             float* __restrict__ out) {
    const int j   = blockIdx.x;
    const int tid = threadIdx.x;
    const float cnt_new = g_cnt[j];
    const float cema = MU * code_count_in[j] + OMU * cnt_new;
    const bool  usage = (cema >= 1.0f);
    const float den = fmaxf(cema, 1e-10f);
    const int   rn = j >> 10;
    const int   rt = j & 1023;

    for (int c = tid; c < CC; c += 256) {
        float sema = MU * code_sum_in[(size_t)j * CC + c] + OMU * g_sum[(size_t)j * CC + c];
        float upd  = sema / den;
        float repl = x[(size_t)rn * CC * TT + (size_t)c * TT + rt];
        out[OFF_CB   + (size_t)j * CC + c] = usage ? upd : repl;
        out[OFF_SEMA + (size_t)j * CC + c] = sema;
    }
    if (tid == 0) out[OFF_CEMA + j] = cema;

    if (j == 0) {
        __shared__ float sRed[256];
        float s = 0.0f;
        const float inv_total = 1.0f / (32768.0f + 1e-10f);
        for (int q = tid; q < NB; q += 256) {
            float p = g_cnt[q] * inv_total;
            s += p * logf(p + 1e-7f);
        }
        sRed[tid] = s;
        __syncthreads();
        for (int o = 128; o > 0; o >>= 1) {
            if (tid < o) sRed[tid] += sRed[tid + o];
            __syncthreads();
        }
        if (tid == 0) {
            out[OFF_PERP] = expf(-sRed[0]);
            out[OFF_LOSS] = g_loss * (1.0f / 16777216.0f);
        }
    }
}

// ----------------------------------------------------------------
extern "C" void kernel_launch(void* const* d_in, const int* in_sizes, int n_in,
                              void* d_out, int out_size) {
    const float* x             = (const float*)d_in[0];
    const float* codebook      = (const float*)d_in[1];
    const float* code_sum_in   = (const float*)d_in[2];
    const float* code_count_in = (const float*)d_in[3];
    float* out = (float*)d_out;

    cudaFuncSetAttribute(k_hmma, cudaFuncAttributeMaxDynamicSharedMemorySize, HMMA_SMEM);

    {
        const int total = NB * CC + NB + 1;
        k_zero<<<(total + 255) / 256, 256>>>();
    }
    k_convert_x<<<4096, 256>>>(x);
    k_convert_cb<<<256, 256>>>(codebook);
    k_hmma<<<NTOK / 128, 128, HMMA_SMEM>>>(x, codebook, out);
    k_ema<<<NB, 256>>>(x, code_sum_in, code_count_in, out);
}

// round 13
// speedup vs baseline: 1.1172x; 1.1172x over previous
#include <cuda_runtime.h>
#include <cuda_bf16.h>
#include <cstdint>

// Problem constants
#define NN   32
#define CC   512
#define TT   1024
#define NTOK 32768            // NN*TT
#define NB   2048
#define MU   0.99f
#define OMU  0.01f
#define MARGIN 12.0f
#define LCAP 3072

// Output layout (concatenated, all f32)
#define OFF_XD    ((size_t)0)
#define OFF_LOSS  ((size_t)16777216)
#define OFF_PERP  ((size_t)16777217)
#define OFF_CB    ((size_t)16777218)
#define OFF_SEMA  ((size_t)17825794)
#define OFF_CEMA  ((size_t)18874370)

// ---------------- device scratch (no allocs allowed) ----------------
__device__ float g_cbnorm[NB];
__device__ float g_sum[(size_t)NB * CC];
__device__ float g_cnt[NB];
__device__ float g_loss;
__device__ __align__(16) __nv_bfloat16 g_xhi[(size_t)NTOK * CC];
__device__ __align__(16) float         g_xT [(size_t)NTOK * CC];   // fp32 transposed x
__device__ __align__(16) __nv_bfloat16 g_bhi[(size_t)NB * CC];

// ---------------- PTX helpers ----------------
__device__ __forceinline__ uint32_t smem_u32(const void* p) {
    uint32_t a;
    asm("{ .reg .u64 t; cvta.to.shared.u64 t, %1; cvt.u32.u64 %0, t; }" : "=r"(a) : "l"(p));
    return a;
}
__device__ __forceinline__ void cp16(uint32_t dst, const void* src) {
    asm volatile("cp.async.cg.shared.global [%0], [%1], 16;" :: "r"(dst), "l"(src));
}
__device__ __forceinline__ void ldmx4(uint32_t* r, uint32_t addr) {
    asm volatile("ldmatrix.sync.aligned.m8n8.x4.shared.b16 {%0,%1,%2,%3}, [%4];"
                 : "=r"(r[0]), "=r"(r[1]), "=r"(r[2]), "=r"(r[3]) : "r"(addr));
}
__device__ __forceinline__ void mma16816(float* d, const uint32_t* a, const uint32_t* b) {
    asm volatile(
        "mma.sync.aligned.m16n8k16.row.col.f32.bf16.bf16.f32 "
        "{%0,%1,%2,%3}, {%4,%5,%6,%7}, {%8,%9}, {%0,%1,%2,%3};"
        : "+f"(d[0]), "+f"(d[1]), "+f"(d[2]), "+f"(d[3])
        : "r"(a[0]), "r"(a[1]), "r"(a[2]), "r"(a[3]), "r"(b[0]), "r"(b[1]));
}
// order-preserving float<->uint
__device__ __forceinline__ unsigned f2u(float f) {
    unsigned u = __float_as_uint(f);
    return (u & 0x80000000u) ? ~u : (u | 0x80000000u);
}
__device__ __forceinline__ float u2f(unsigned u) {
    return (u & 0x80000000u) ? __uint_as_float(u & 0x7FFFFFFFu)
                             : __uint_as_float(~u);
}

// ---------------- zero scratch ----------------
__global__ void k_zero() {
    int i = blockIdx.x * blockDim.x + threadIdx.x;
    const int total = NB * CC + NB + 1;
    for (; i < total; i += gridDim.x * blockDim.x) {
        if (i < NB * CC)           g_sum[i] = 0.0f;
        else if (i < NB * CC + NB) g_cnt[i - NB * CC] = 0.0f;
        else                       g_loss = 0.0f;
    }
}

// ---------------- codebook: bf16 hi + exact fp32 norms ----------
__global__ __launch_bounds__(256) void k_convert_cb(const float* __restrict__ cb) {
    int wid  = (blockIdx.x * blockDim.x + threadIdx.x) >> 5;
    int lane = threadIdx.x & 31;
    if (wid >= NB) return;
    const float* row = cb + (size_t)wid * CC;
    float s = 0.0f;
    #pragma unroll
    for (int i = 0; i < CC / 32; i++) {
        float v = row[lane + 32 * i];
        s += v * v;
        g_bhi[(size_t)wid * CC + lane + 32 * i] = __float2bfloat16(v);
    }
    #pragma unroll
    for (int o = 16; o > 0; o >>= 1) s += __shfl_down_sync(0xFFFFFFFFu, s, o);
    if (lane == 0) g_cbnorm[wid] = s;
}

// ---------------- transpose x: bf16 hi + fp32 copy ----------------
__global__ __launch_bounds__(256) void k_convert_x(const float* __restrict__ x) {
    __shared__ float s[64][65];
    const int b = blockIdx.x;
    const int ttile = b & 15, ctile = (b >> 4) & 7, n = b >> 7;
    const int c0 = ctile * 64, t0 = ttile * 64;
    const int tid = threadIdx.x;
    const float* xb = x + (size_t)n * CC * TT;
    #pragma unroll
    for (int q = 0; q < 16; q++) {
        int idx = tid + 256 * q;
        int r = idx >> 6, col = idx & 63;
        s[r][col] = xb[(size_t)(c0 + r) * TT + t0 + col];
    }
    __syncthreads();
    #pragma unroll
    for (int q = 0; q < 16; q++) {
        int idx = tid + 256 * q;
        int tr = idx >> 6, cc = idx & 63;
        float v = s[cc][tr];
        size_t token = (size_t)(n * 1024 + t0 + tr);
        g_xhi[token * 512 + c0 + cc] = __float2bfloat16(v);
        g_xT [token * 512 + c0 + cc] = v;
    }
}

// ---------------- approx GEMM + candidate collect + exact rescore + scatter
// Block: 128 tokens x 128-code tile, 16 code tiles, K = 512 (hi only).
// 4 warps (2x2), warp tile 64x64. 3-stage cp.async ring, BK = 64.
#define STAGE 32768
#define HMMA_SMEM (3 * STAGE)
#define NSTEPS 128              // 16 nj * 8 k-steps

__device__ __forceinline__ void load_tile(int tid, uint32_t dyn, int it, int m0) {
    const int nj = it >> 3;
    const int kt = it & 7;
    const __nv_bfloat16* Asrc = g_xhi + (size_t)m0 * 512 + kt * 64;
    const __nv_bfloat16* Bsrc = g_bhi + (size_t)nj * 128 * 512 + kt * 64;
    const uint32_t abase = dyn + (uint32_t)(it % 3) * STAGE;
    const uint32_t bbase = abase + 16384u;
    #pragma unroll
    for (int q = 0; q < 8; q++) {
        int op = tid + 128 * q;
        int row = op >> 3, c = op & 7;
        cp16(abase + row * 128 + (((c ^ row) & 7) << 4), Asrc + (size_t)row * 512 + c * 8);
    }
    #pragma unroll
    for (int q = 0; q < 8; q++) {
        int op = tid + 128 * q;
        int row = op >> 3, c = op & 7;
        cp16(bbase + row * 128 + (((c ^ row) & 7) << 4), Bsrc + (size_t)row * 512 + c * 8);
    }
    asm volatile("cp.async.commit_group;" ::: "memory");
}

__global__ __launch_bounds__(128, 2) void k_hmma(const float* __restrict__ x,
                                                 const float* __restrict__ cb,
                                                 float* __restrict__ out) {
    extern __shared__ char dsm[];
    __shared__ unsigned sMinU[128];            // running approx min (ordered uint)
    __shared__ float    sNorm[128];            // this nj-tile's codebook norms
    __shared__ unsigned long long sKeyE[128];  // exact (d,j) keys
    __shared__ unsigned sList[LCAP];           // candidates: row<<16 | j
    __shared__ int  sCnt;
    __shared__ int  sIdx[128];
    __shared__ float sRed[128];

    const uint32_t dyn = smem_u32(dsm);
    const int tid  = threadIdx.x;
    const int lane = tid & 31;
    const int warp = tid >> 5;
    const int wm   = warp >> 1;      // 0..1
    const int wn   = warp & 1;       // 0..1
    const int m0   = blockIdx.x * 128;
    const float INF = __int_as_float(0x7f800000);

    // init shared state
    sMinU[tid] = 0xFFFFFFFFu;
    sKeyE[tid] = 0xFFFFFFFFFFFFFFFFULL;
    if (tid == 0) sCnt = 0;

    // ldmatrix per-thread addressing
    const int sub = lane >> 3, l7 = lane & 7;
    const int a_rowadd = ((sub & 1) << 3) + l7;
    const int a_cadd   = sub >> 1;
    const int b_rowadd = ((sub >> 1) << 3) + l7;
    const int b_cadd   = sub & 1;
    uint32_t aRowB[4], bRowB[4];
    #pragma unroll
    for (int mt = 0; mt < 4; mt++) aRowB[mt] = (uint32_t)(wm * 64 + mt * 16 + a_rowadd) * 128u;
    #pragma unroll
    for (int p = 0; p < 4; p++)    bRowB[p] = (uint32_t)(wn * 64 + p * 16 + b_rowadd) * 128u;

    float acc[4][8][4];
    #pragma unroll
    for (int mt = 0; mt < 4; mt++)
        #pragma unroll
        for (int nt = 0; nt < 8; nt++)
            #pragma unroll
            for (int r = 0; r < 4; r++) acc[mt][nt][r] = 0.0f;

    load_tile(tid, dyn, 0, m0);
    load_tile(tid, dyn, 1, m0);

    for (int it = 0; it < NSTEPS; it++) {
        if (it + 1 < NSTEPS) asm volatile("cp.async.wait_group 1;" ::: "memory");
        else                 asm volatile("cp.async.wait_group 0;" ::: "memory");
        __syncthreads();
        if (it + 2 < NSTEPS) load_tile(tid, dyn, it + 2, m0);

        // first k-step of a code tile: stage its norms into SMEM
        if ((it & 7) == 0) sNorm[tid] = g_cbnorm[(it >> 3) * 128 + tid];

        const uint32_t abase = dyn + (uint32_t)(it % 3) * STAGE;
        const uint32_t bbase = abase + 16384u;

        #pragma unroll
        for (int kk = 0; kk < 4; kk++) {
            uint32_t afr[4][4], bfr[4][4];
            #pragma unroll
            for (int mt = 0; mt < 4; mt++)
                ldmx4(afr[mt], abase + aRowB[mt] + ((((kk * 2 + a_cadd) ^ l7) & 7) << 4));
            #pragma unroll
            for (int p = 0; p < 4; p++)
                ldmx4(bfr[p], bbase + bRowB[p] + ((((kk * 2 + b_cadd) ^ l7) & 7) << 4));
            #pragma unroll
            for (int mt = 0; mt < 4; mt++)
                #pragma unroll
                for (int nt = 0; nt < 8; nt++)
                    mma16816(acc[mt][nt], afr[mt], &bfr[nt >> 1][(nt & 1) * 2]);
        }

        // end of one nj code-tile: single-pass fold + cheap candidate push
        if ((it & 7) == 7) {
            const int njbase = (it >> 3) * 128;

            if (it == 7) {
                // nj==0 only: pre-fold so thresholds are finite
                #pragma unroll
                for (int mt = 0; mt < 4; mt++) {
                    #pragma unroll
                    for (int rh = 0; rh < 2; rh++) {
                        float bv = INF;
                        #pragma unroll
                        for (int nt = 0; nt < 8; nt++) {
                            #pragma unroll
                            for (int c = 0; c < 2; c++) {
                                int jl = wn * 64 + nt * 8 + ((lane & 3) << 1) + c;
                                bv = fminf(bv, fmaf(-2.0f, acc[mt][nt][rh * 2 + c], sNorm[jl]));
                            }
                        }
                        bv = fminf(bv, __shfl_xor_sync(0xFFFFFFFFu, bv, 1));
                        bv = fminf(bv, __shfl_xor_sync(0xFFFFFFFFu, bv, 2));
                        if ((lane & 3) == 0)
                            atomicMin(&sMinU[wm * 64 + mt * 16 + rh * 8 + (lane >> 2)], f2u(bv));
                    }
                }
                __syncthreads();
            }

            // combined fold + collect: stale-min threshold is provably safe
            #pragma unroll
            for (int mt = 0; mt < 4; mt++) {
                #pragma unroll
                for (int rh = 0; rh < 2; rh++) {
                    const int row = wm * 64 + mt * 16 + rh * 8 + (lane >> 2);
                    const float thr = u2f(sMinU[row]) + MARGIN;
                    float bv = INF;
                    #pragma unroll
                    for (int nt = 0; nt < 8; nt++) {
                        #pragma unroll
                        for (int c = 0; c < 2; c++) {
                            int jl = wn * 64 + nt * 8 + ((lane & 3) << 1) + c;
                            float d = fmaf(-2.0f, acc[mt][nt][rh * 2 + c], sNorm[jl]);
                            bv = fminf(bv, d);
                            if (d <= thr) {
                                int pos = atomicAdd(&sCnt, 1);
                                if (pos < LCAP)
                                    sList[pos] = ((unsigned)row << 16)
                                               | (unsigned)(njbase + jl);
                            }
                        }
                    }
                    bv = fminf(bv, __shfl_xor_sync(0xFFFFFFFFu, bv, 1));
                    bv = fminf(bv, __shfl_xor_sync(0xFFFFFFFFu, bv, 2));
                    if ((lane & 3) == 0) atomicMin(&sMinU[row], f2u(bv));
                }
            }

            #pragma unroll
            for (int mt = 0; mt < 4; mt++)
                #pragma unroll
                for (int nt = 0; nt < 8; nt++)
                    #pragma unroll
                    for (int r = 0; r < 4; r++) acc[mt][nt][r] = 0.0f;
        }
    }

    __syncthreads();
    // -------- pass 2: exact fp32 rescore of candidates ------------------
    {
        const int cnt = min(sCnt, LCAP);
        for (int i = warp; i < cnt; i += 4) {
            unsigned e = sList[i];
            int row = e >> 16;
            int j   = e & 0xFFFF;
            const float4* xr = (const float4*)(g_xT + (size_t)(m0 + row) * 512);
            const float4* cr = (const float4*)(cb  + (size_t)j * 512);
            float s = 0.0f;
            #pragma unroll
            for (int q = 0; q < 4; q++) {
                float4 a = xr[lane + 32 * q];
                float4 b = cr[lane + 32 * q];
                s += a.x * b.x + a.y * b.y + a.z * b.z + a.w * b.w;
            }
            #pragma unroll
            for (int o = 16; o > 0; o >>= 1) s += __shfl_xor_sync(0xFFFFFFFFu, s, o);
            if (lane == 0) {
                float d = fmaf(-2.0f, s, g_cbnorm[j]);
                unsigned long long key = ((unsigned long long)f2u(d) << 32) | (unsigned)j;
                atomicMin(&sKeyE[row], key);
            }
        }
    }
    __syncthreads();
    {
        int id = (int)(sKeyE[tid] & 0xFFFFFFFFu);
        sIdx[tid] = id;
        atomicAdd(&g_cnt[id], 1.0f);
    }
    __syncthreads();

    // -------- fused scatter: this CTA's 128 tokens, all 512 channels -----
    {
        const int n  = m0 >> 10;
        const int t0 = m0 & 1023;
        const int idx  = sIdx[tid];
        const float* xb = x + (size_t)n * CC * TT + t0 + tid;
        float* ob = out + OFF_XD + (size_t)n * CC * TT + t0 + tid;
        const float* cbrow = cb + (size_t)idx * CC;
        float* srow = g_sum + (size_t)idx * CC;

        float loss = 0.0f;
        #pragma unroll 8
        for (int k = 0; k < 128; k++) {
            int c = k * 4;
            float4 cv = *(const float4*)(cbrow + c);
            float x0 = __ldcs(xb + (size_t)(c + 0) * TT);
            float x1 = __ldcs(xb + (size_t)(c + 1) * TT);
            float x2 = __ldcs(xb + (size_t)(c + 2) * TT);
            float x3 = __ldcs(xb + (size_t)(c + 3) * TT);
            float d0 = x0 - cv.x, d1 = x1 - cv.y, d2 = x2 - cv.z, d3 = x3 - cv.w;
            loss = fmaf(d0, d0, loss); loss = fmaf(d1, d1, loss);
            loss = fmaf(d2, d2, loss); loss = fmaf(d3, d3, loss);
            __stcs(ob + (size_t)(c + 0) * TT, x0 + (cv.x - x0));
            __stcs(ob + (size_t)(c + 1) * TT, x1 + (cv.y - x1));
            __stcs(ob + (size_t)(c + 2) * TT, x2 + (cv.z - x2));
            __stcs(ob + (size_t)(c + 3) * TT, x3 + (cv.w - x3));
            asm volatile("red.global.add.v4.f32 [%0], {%1, %2, %3, %4};"
                         :: "l"(srow + c), "f"(x0), "f"(x1), "f"(x2), "f"(x3) : "memory");
        }

        sRed[tid] = loss;
        __syncthreads();
        for (int o = 64; o > 0; o >>= 1) {
            if (tid < o) sRed[tid] += sRed[tid + o];
            __syncthreads();
        }
        if (tid == 0) atomicAdd(&g_loss, sRed[0]);
    }
}

// ---------------- EMA + codebook (+ scalars in block 0) ----------------
__global__ __launch_bounds__(256) void k_ema(const float* __restrict__ x,
                                             const float* __restrict__ code_sum_in,
                                             const float* __restrict__ code_count_in,
                                             float* __restrict__ out) {
    const int j   = blockIdx.x;
    const int tid = threadIdx.x;
    const float cnt_new = g_cnt[j];
    const float cema = MU * code_count_in[j] + OMU * cnt_new;
    const bool  usage = (cema >= 1.0f);
    const float den = fmaxf(cema, 1e-10f);
    const int   rn = j >> 10;
    const int   rt = j & 1023;

    for (int c = tid; c < CC; c += 256) {
        float sema = MU * code_sum_in[(size_t)j * CC + c] + OMU * g_sum[(size_t)j * CC + c];
        float upd  = sema / den;
        float repl = x[(size_t)rn * CC * TT + (size_t)c * TT + rt];
        out[OFF_CB   + (size_t)j * CC + c] = usage ? upd : repl;
        out[OFF_SEMA + (size_t)j * CC + c] = sema;
    }
    if (tid == 0) out[OFF_CEMA + j] = cema;

    if (j == 0) {
        __shared__ float sRed[256];
        float s = 0.0f;
        const float inv_total = 1.0f / (32768.0f + 1e-10f);
        for (int q = tid; q < NB; q += 256) {
            float p = g_cnt[q] * inv_total;
            s += p * logf(p + 1e-7f);
        }
        sRed[tid] = s;
        __syncthreads();
        for (int o = 128; o > 0; o >>= 1) {
            if (tid < o) sRed[tid] += sRed[tid + o];
            __syncthreads();
        }
        if (tid == 0) {
            out[OFF_PERP] = expf(-sRed[0]);
            out[OFF_LOSS] = g_loss * (1.0f / 16777216.0f);
        }
    }
}

// ----------------------------------------------------------------
extern "C" void kernel_launch(void* const* d_in, const int* in_sizes, int n_in,
                              void* d_out, int out_size) {
    const float* x             = (const float*)d_in[0];
    const float* codebook      = (const float*)d_in[1];
    const float* code_sum_in   = (const float*)d_in[2];
    const float* code_count_in = (const float*)d_in[3];
    float* out = (float*)d_out;

    cudaFuncSetAttribute(k_hmma, cudaFuncAttributeMaxDynamicSharedMemorySize, HMMA_SMEM);

    {
        const int total = NB * CC + NB + 1;
        k_zero<<<(total + 255) / 256, 256>>>();
    }
    k_convert_x<<<4096, 256>>>(x);
    k_convert_cb<<<256, 256>>>(codebook);
    k_hmma<<<NTOK / 128, 128, HMMA_SMEM>>>(x, codebook, out);
    k_ema<<<NB, 256>>>(x, code_sum_in, code_count_in, out);
}

// round 15
// speedup vs baseline: 1.3753x; 1.2310x over previous
#include <cuda_runtime.h>
#include <cuda_bf16.h>
#include <cstdint>

// Problem constants
#define NN   32
#define CC   512
#define TT   1024
#define NTOK 32768            // NN*TT
#define NB   2048
#define MU   0.99f
#define OMU  0.01f
#define MARGIN 12.0f
#define LCAP 3072

// Output layout (concatenated, all f32)
#define OFF_XD    ((size_t)0)
#define OFF_LOSS  ((size_t)16777216)
#define OFF_PERP  ((size_t)16777217)
#define OFF_CB    ((size_t)16777218)
#define OFF_SEMA  ((size_t)17825794)
#define OFF_CEMA  ((size_t)18874370)

// ---------------- device scratch (no allocs allowed) ----------------
__device__ float g_cbnorm[NB];
__device__ float g_sum[(size_t)NB * CC];
__device__ float g_cnt[NB];
__device__ float g_loss;
__device__ __align__(16) __nv_bfloat16 g_xhi[(size_t)NTOK * CC];
__device__ __align__(16) float         g_xT [(size_t)NTOK * CC];   // fp32 transposed x
__device__ __align__(16) __nv_bfloat16 g_bhi[(size_t)NB * CC];

// ---------------- PTX helpers ----------------
__device__ __forceinline__ uint32_t smem_u32(const void* p) {
    uint32_t a;
    asm("{ .reg .u64 t; cvta.to.shared.u64 t, %1; cvt.u32.u64 %0, t; }" : "=r"(a) : "l"(p));
    return a;
}
__device__ __forceinline__ void cp16(uint32_t dst, const void* src) {
    asm volatile("cp.async.cg.shared.global [%0], [%1], 16;" :: "r"(dst), "l"(src));
}
__device__ __forceinline__ void ldmx4(uint32_t* r, uint32_t addr) {
    asm volatile("ldmatrix.sync.aligned.m8n8.x4.shared.b16 {%0,%1,%2,%3}, [%4];"
                 : "=r"(r[0]), "=r"(r[1]), "=r"(r[2]), "=r"(r[3]) : "r"(addr));
}
__device__ __forceinline__ void mma16816(float* d, const uint32_t* a, const uint32_t* b) {
    asm volatile(
        "mma.sync.aligned.m16n8k16.row.col.f32.bf16.bf16.f32 "
        "{%0,%1,%2,%3}, {%4,%5,%6,%7}, {%8,%9}, {%0,%1,%2,%3};"
        : "+f"(d[0]), "+f"(d[1]), "+f"(d[2]), "+f"(d[3])
        : "r"(a[0]), "r"(a[1]), "r"(a[2]), "r"(a[3]), "r"(b[0]), "r"(b[1]));
}
// order-preserving float<->uint
__device__ __forceinline__ unsigned f2u(float f) {
    unsigned u = __float_as_uint(f);
    return (u & 0x80000000u) ? ~u : (u | 0x80000000u);
}
__device__ __forceinline__ float u2f(unsigned u) {
    return (u & 0x80000000u) ? __uint_as_float(u & 0x7FFFFFFFu)
                             : __uint_as_float(~u);
}

// ---------------- zero scratch ----------------
__global__ void k_zero() {
    int i = blockIdx.x * blockDim.x + threadIdx.x;
    const int total = NB * CC + NB + 1;
    for (; i < total; i += gridDim.x * blockDim.x) {
        if (i < NB * CC)           g_sum[i] = 0.0f;
        else if (i < NB * CC + NB) g_cnt[i - NB * CC] = 0.0f;
        else                       g_loss = 0.0f;
    }
}

// ---------------- codebook: bf16 hi + exact fp32 norms ----------
__global__ __launch_bounds__(256) void k_convert_cb(const float* __restrict__ cb) {
    int wid  = (blockIdx.x * blockDim.x + threadIdx.x) >> 5;
    int lane = threadIdx.x & 31;
    if (wid >= NB) return;
    const float* row = cb + (size_t)wid * CC;
    float s = 0.0f;
    #pragma unroll
    for (int i = 0; i < CC / 32; i++) {
        float v = row[lane + 32 * i];
        s += v * v;
        g_bhi[(size_t)wid * CC + lane + 32 * i] = __float2bfloat16(v);
    }
    #pragma unroll
    for (int o = 16; o > 0; o >>= 1) s += __shfl_down_sync(0xFFFFFFFFu, s, o);
    if (lane == 0) g_cbnorm[wid] = s;
}

// ---------------- transpose x: bf16 hi + fp32 copy ----------------
__global__ __launch_bounds__(256) void k_convert_x(const float* __restrict__ x) {
    __shared__ float s[64][65];
    const int b = blockIdx.x;
    const int ttile = b & 15, ctile = (b >> 4) & 7, n = b >> 7;
    const int c0 = ctile * 64, t0 = ttile * 64;
    const int tid = threadIdx.x;
    const float* xb = x + (size_t)n * CC * TT;
    #pragma unroll
    for (int q = 0; q < 16; q++) {
        int idx = tid + 256 * q;
        int r = idx >> 6, col = idx & 63;
        s[r][col] = xb[(size_t)(c0 + r) * TT + t0 + col];
    }
    __syncthreads();
    #pragma unroll
    for (int q = 0; q < 16; q++) {
        int idx = tid + 256 * q;
        int tr = idx >> 6, cc = idx & 63;
        float v = s[cc][tr];
        size_t token = (size_t)(n * 1024 + t0 + tr);
        g_xhi[token * 512 + c0 + cc] = __float2bfloat16(v);
        g_xT [token * 512 + c0 + cc] = v;
    }
}

// ---------------- approx GEMM + candidate collect + exact rescore + scatter
// Block: 128 tokens x 128-code tile, 16 code tiles, K = 512 (hi only).
// 8 warps (2x4), warp tile 64x32. 3-stage cp.async ring, BK = 64. 256 thr.
#define STAGE 32768
#define HMMA_SMEM (3 * STAGE)
#define NSTEPS 128              // 16 nj * 8 k-steps

__device__ __forceinline__ void load_tile(int tid, uint32_t dyn, int it, int m0) {
    const int nj = it >> 3;
    const int kt = it & 7;
    const __nv_bfloat16* Asrc = g_xhi + (size_t)m0 * 512 + kt * 64;
    const __nv_bfloat16* Bsrc = g_bhi + (size_t)nj * 128 * 512 + kt * 64;
    const uint32_t abase = dyn + (uint32_t)(it % 3) * STAGE;
    const uint32_t bbase = abase + 16384u;
    #pragma unroll
    for (int q = 0; q < 4; q++) {
        int op = tid + 256 * q;
        int row = op >> 3, c = op & 7;
        cp16(abase + row * 128 + (((c ^ row) & 7) << 4), Asrc + (size_t)row * 512 + c * 8);
    }
    #pragma unroll
    for (int q = 0; q < 4; q++) {
        int op = tid + 256 * q;
        int row = op >> 3, c = op & 7;
        cp16(bbase + row * 128 + (((c ^ row) & 7) << 4), Bsrc + (size_t)row * 512 + c * 8);
    }
    asm volatile("cp.async.commit_group;" ::: "memory");
}

__global__ __launch_bounds__(256, 2) void k_hmma(const float* __restrict__ x,
                                                 const float* __restrict__ cb,
                                                 float* __restrict__ out) {
    extern __shared__ char dsm[];
    __shared__ unsigned sMinU[128];            // running approx min (ordered uint)
    __shared__ float    sNorm[128];            // this nj-tile's codebook norms
    __shared__ unsigned long long sKeyE[128];  // exact (d,j) keys
    __shared__ unsigned sList[LCAP];           // candidates: row<<16 | j
    __shared__ int  sCnt;
    __shared__ int  sIdx[128];
    __shared__ float sRed[256];

    const uint32_t dyn = smem_u32(dsm);
    const int tid  = threadIdx.x;
    const int lane = tid & 31;
    const int warp = tid >> 5;
    const int wm   = warp >> 2;      // 0..1
    const int wn   = warp & 3;       // 0..3
    const int m0   = blockIdx.x * 128;
    const float INF = __int_as_float(0x7f800000);

    // init shared state
    if (tid < 128) {
        sMinU[tid] = 0xFFFFFFFFu;
        sKeyE[tid] = 0xFFFFFFFFFFFFFFFFULL;
    }
    if (tid == 0) sCnt = 0;

    // ldmatrix per-thread addressing
    const int sub = lane >> 3, l7 = lane & 7;
    const int a_rowadd = ((sub & 1) << 3) + l7;
    const int a_cadd   = sub >> 1;
    const int b_rowadd = ((sub >> 1) << 3) + l7;
    const int b_cadd   = sub & 1;
    uint32_t aRowB[4], bRowB[2];
    #pragma unroll
    for (int mt = 0; mt < 4; mt++) aRowB[mt] = (uint32_t)(wm * 64 + mt * 16 + a_rowadd) * 128u;
    #pragma unroll
    for (int p = 0; p < 2; p++)    bRowB[p] = (uint32_t)(wn * 32 + p * 16 + b_rowadd) * 128u;

    float acc[4][4][4];
    #pragma unroll
    for (int mt = 0; mt < 4; mt++)
        #pragma unroll
        for (int nt = 0; nt < 4; nt++)
            #pragma unroll
            for (int r = 0; r < 4; r++) acc[mt][nt][r] = 0.0f;

    load_tile(tid, dyn, 0, m0);
    load_tile(tid, dyn, 1, m0);

    for (int it = 0; it < NSTEPS; it++) {
        if (it + 1 < NSTEPS) asm volatile("cp.async.wait_group 1;" ::: "memory");
        else                 asm volatile("cp.async.wait_group 0;" ::: "memory");
        __syncthreads();
        if (it + 2 < NSTEPS) load_tile(tid, dyn, it + 2, m0);

        // first k-step of a code tile: stage its norms into SMEM
        if ((it & 7) == 0 && tid < 128) sNorm[tid] = g_cbnorm[(it >> 3) * 128 + tid];

        const uint32_t abase = dyn + (uint32_t)(it % 3) * STAGE;
        const uint32_t bbase = abase + 16384u;

        #pragma unroll
        for (int kk = 0; kk < 4; kk++) {
            uint32_t afr[4][4], bfr[2][4];
            #pragma unroll
            for (int mt = 0; mt < 4; mt++)
                ldmx4(afr[mt], abase + aRowB[mt] + ((((kk * 2 + a_cadd) ^ l7) & 7) << 4));
            #pragma unroll
            for (int p = 0; p < 2; p++)
                ldmx4(bfr[p], bbase + bRowB[p] + ((((kk * 2 + b_cadd) ^ l7) & 7) << 4));
            #pragma unroll
            for (int mt = 0; mt < 4; mt++)
                #pragma unroll
                for (int nt = 0; nt < 4; nt++)
                    mma16816(acc[mt][nt], afr[mt], &bfr[nt >> 1][(nt & 1) * 2]);
        }

        // end of one nj code-tile: single-pass fold + cheap candidate push
        if ((it & 7) == 7) {
            const int njbase = (it >> 3) * 128;

            if (it == 7) {
                // nj==0 only: pre-fold so thresholds are finite
                #pragma unroll
                for (int mt = 0; mt < 4; mt++) {
                    #pragma unroll
                    for (int rh = 0; rh < 2; rh++) {
                        float bv = INF;
                        #pragma unroll
                        for (int nt = 0; nt < 4; nt++) {
                            #pragma unroll
                            for (int c = 0; c < 2; c++) {
                                int jl = wn * 32 + nt * 8 + ((lane & 3) << 1) + c;
                                bv = fminf(bv, fmaf(-2.0f, acc[mt][nt][rh * 2 + c], sNorm[jl]));
                            }
                        }
                        bv = fminf(bv, __shfl_xor_sync(0xFFFFFFFFu, bv, 1));
                        bv = fminf(bv, __shfl_xor_sync(0xFFFFFFFFu, bv, 2));
                        if ((lane & 3) == 0)
                            atomicMin(&sMinU[wm * 64 + mt * 16 + rh * 8 + (lane >> 2)], f2u(bv));
                    }
                }
                __syncthreads();
            }

            // combined fold + collect: stale-min threshold is provably safe
            #pragma unroll
            for (int mt = 0; mt < 4; mt++) {
                #pragma unroll
                for (int rh = 0; rh < 2; rh++) {
                    const int row = wm * 64 + mt * 16 + rh * 8 + (lane >> 2);
                    const float thr = u2f(sMinU[row]) + MARGIN;
                    float bv = INF;
                    #pragma unroll
                    for (int nt = 0; nt < 4; nt++) {
                        #pragma unroll
                        for (int c = 0; c < 2; c++) {
                            int jl = wn * 32 + nt * 8 + ((lane & 3) << 1) + c;
                            float d = fmaf(-2.0f, acc[mt][nt][rh * 2 + c], sNorm[jl]);
                            bv = fminf(bv, d);
                            if (d <= thr) {
                                int pos = atomicAdd(&sCnt, 1);
                                if (pos < LCAP)
                                    sList[pos] = ((unsigned)row << 16)
                                               | (unsigned)(njbase + jl);
                            }
                        }
                    }
                    bv = fminf(bv, __shfl_xor_sync(0xFFFFFFFFu, bv, 1));
                    bv = fminf(bv, __shfl_xor_sync(0xFFFFFFFFu, bv, 2));
                    if ((lane & 3) == 0) atomicMin(&sMinU[row], f2u(bv));
                }
            }

            #pragma unroll
            for (int mt = 0; mt < 4; mt++)
                #pragma unroll
                for (int nt = 0; nt < 4; nt++)
                    #pragma unroll
                    for (int r = 0; r < 4; r++) acc[mt][nt][r] = 0.0f;
        }
    }

    __syncthreads();
    // -------- pass 2: exact fp32 rescore of candidates (8 warps) ---------
    {
        const int cnt = min(sCnt, LCAP);
        for (int i = warp; i < cnt; i += 8) {
            unsigned e = sList[i];
            int row = e >> 16;
            int j   = e & 0xFFFF;
            const float4* xr = (const float4*)(g_xT + (size_t)(m0 + row) * 512);
            const float4* cr = (const float4*)(cb  + (size_t)j * 512);
            float s = 0.0f;
            #pragma unroll
            for (int q = 0; q < 4; q++) {
                float4 a = xr[lane + 32 * q];
                float4 b = cr[lane + 32 * q];
                s += a.x * b.x + a.y * b.y + a.z * b.z + a.w * b.w;
            }
            #pragma unroll
            for (int o = 16; o > 0; o >>= 1) s += __shfl_xor_sync(0xFFFFFFFFu, s, o);
            if (lane == 0) {
                float d = fmaf(-2.0f, s, g_cbnorm[j]);
                unsigned long long key = ((unsigned long long)f2u(d) << 32) | (unsigned)j;
                atomicMin(&sKeyE[row], key);
            }
        }
    }
    __syncthreads();
    if (tid < 128) {
        int id = (int)(sKeyE[tid] & 0xFFFFFFFFu);
        sIdx[tid] = id;
        atomicAdd(&g_cnt[id], 1.0f);
    }
    __syncthreads();

    // -------- fused scatter: 128 tokens x 512 channels, 256 threads ------
    {
        const int n  = m0 >> 10;
        const int t0 = m0 & 1023;
        const int tt   = tid & 127;
        const int half = tid >> 7;              // c-offset 0 or 4
        const int idx  = sIdx[tt];
        const float* xb = x + (size_t)n * CC * TT + t0 + tt;
        float* ob = out + OFF_XD + (size_t)n * CC * TT + t0 + tt;
        const float* cbrow = cb + (size_t)idx * CC;
        float* srow = g_sum + (size_t)idx * CC;

        float loss = 0.0f;
        #pragma unroll 8
        for (int k = 0; k < 64; k++) {
            int c = half * 4 + k * 8;
            float4 cv = *(const float4*)(cbrow + c);
            float x0 = __ldcs(xb + (size_t)(c + 0) * TT);
            float x1 = __ldcs(xb + (size_t)(c + 1) * TT);
            float x2 = __ldcs(xb + (size_t)(c + 2) * TT);
            float x3 = __ldcs(xb + (size_t)(c + 3) * TT);
            float d0 = x0 - cv.x, d1 = x1 - cv.y, d2 = x2 - cv.z, d3 = x3 - cv.w;
            loss = fmaf(d0, d0, loss); loss = fmaf(d1, d1, loss);
            loss = fmaf(d2, d2, loss); loss = fmaf(d3, d3, loss);
            __stcs(ob + (size_t)(c + 0) * TT, x0 + (cv.x - x0));
            __stcs(ob + (size_t)(c + 1) * TT, x1 + (cv.y - x1));
            __stcs(ob + (size_t)(c + 2) * TT, x2 + (cv.z - x2));
            __stcs(ob + (size_t)(c + 3) * TT, x3 + (cv.w - x3));
            asm volatile("red.global.add.v4.f32 [%0], {%1, %2, %3, %4};"
                         :: "l"(srow + c), "f"(x0), "f"(x1), "f"(x2), "f"(x3) : "memory");
        }

        sRed[tid] = loss;
        __syncthreads();
        for (int o = 128; o > 0; o >>= 1) {
            if (tid < o) sRed[tid] += sRed[tid + o];
            __syncthreads();
        }
        if (tid == 0) atomicAdd(&g_loss, sRed[0]);
    }
}

// ---------------- EMA + codebook (+ scalars in block 0) ----------------
__global__ __launch_bounds__(256) void k_ema(const float* __restrict__ x,
                                             const float* __restrict__ code_sum_in,
                                             const float* __restrict__ code_count_in,
                                             float* __restrict__ out) {
    const int j   = blockIdx.x;
    const int tid = threadIdx.x;
    const float cnt_new = g_cnt[j];
    const float cema = MU * code_count_in[j] + OMU * cnt_new;
    const bool  usage = (cema >= 1.0f);
    const float den = fmaxf(cema, 1e-10f);
    const int   rn = j >> 10;
    const int   rt = j & 1023;

    for (int c = tid; c < CC; c += 256) {
        float sema = MU * code_sum_in[(size_t)j * CC + c] + OMU * g_sum[(size_t)j * CC + c];
        float upd  = sema / den;
        float repl = x[(size_t)rn * CC * TT + (size_t)c * TT + rt];
        out[OFF_CB   + (size_t)j * CC + c] = usage ? upd : repl;
        out[OFF_SEMA + (size_t)j * CC + c] = sema;
    }
    if (tid == 0) out[OFF_CEMA + j] = cema;

    if (j == 0) {
        __shared__ float sRed[256];
        float s = 0.0f;
        const float inv_total = 1.0f / (32768.0f + 1e-10f);
        for (int q = tid; q < NB; q += 256) {
            float p = g_cnt[q] * inv_total;
            s += p * logf(p + 1e-7f);
        }
        sRed[tid] = s;
        __syncthreads();
        for (int o = 128; o > 0; o >>= 1) {
            if (tid < o) sRed[tid] += sRed[tid + o];
            __syncthreads();
        }
        if (tid == 0) {
            out[OFF_PERP] = expf(-sRed[0]);
            out[OFF_LOSS] = g_loss * (1.0f / 16777216.0f);
        }
    }
}

// ----------------------------------------------------------------
extern "C" void kernel_launch(void* const* d_in, const int* in_sizes, int n_in,
                              void* d_out, int out_size) {
    const float* x             = (const float*)d_in[0];
    const float* codebook      = (const float*)d_in[1];
    const float* code_sum_in   = (const float*)d_in[2];
    const float* code_count_in = (const float*)d_in[3];
    float* out = (float*)d_out;

    cudaFuncSetAttribute(k_hmma, cudaFuncAttributeMaxDynamicSharedMemorySize, HMMA_SMEM);

    {
        const int total = NB * CC + NB + 1;
        k_zero<<<(total + 255) / 256, 256>>>();
    }
    k_convert_x<<<4096, 256>>>(x);
    k_convert_cb<<<256, 256>>>(codebook);
    k_hmma<<<NTOK / 128, 256, HMMA_SMEM>>>(x, codebook, out);
    k_ema<<<NB, 256>>>(x, code_sum_in, code_count_in, out);
}